// round 15
// baseline (speedup 1.0000x reference)
#include <cuda_runtime.h>

// ---------------------------------------------------------------------------
// SSIM (5x5 Gaussian, sigma=1.5, SAME zero padding), fused single kernel.
// R15 = R11 skeleton with register cuts to reach 5 CTAs/SM (<=102 regs):
//   - wgm eliminated: producers store (s,d)*mask -> OOB smem entries are
//     exact zeros; consumers use unmasked wg.
//   - symmetric weights: g[0]==g[4], g[1]==g[3] (bitwise, outer-product of
//     symmetric g) -> 3 packed weights, add2-paired taps.
//   - running offsets om/oh/ob (+W per step); channel strides are
//     compile-time immediates (c*HW) folded into addressing.
// ---------------------------------------------------------------------------

constexpr int W    = 512;
constexpr int H    = 512;
constexpr int C    = 3;
constexpr int NB   = 16;
constexpr int BX   = 128;   // output columns per block (4 warps x 32)
constexpr int ROWS = 32;    // output rows per block
constexpr int HW   = H * W; // per-channel stride (compile-time)

typedef unsigned long long u64;

__device__ __forceinline__ u64 pk2(float lo, float hi) {
    u64 r;
    asm("mov.b64 %0, {%1, %2};" : "=l"(r) : "f"(lo), "f"(hi));
    return r;
}
__device__ __forceinline__ void up2(u64 v, float& lo, float& hi) {
    asm("mov.b64 {%0, %1}, %2;" : "=f"(lo), "=f"(hi) : "l"(v));
}
__device__ __forceinline__ u64 fma2_(u64 a, u64 b, u64 c) {
    u64 d;
    asm("fma.rn.f32x2 %0, %1, %2, %3;" : "=l"(d) : "l"(a), "l"(b), "l"(c));
    return d;
}
__device__ __forceinline__ u64 mul2_(u64 a, u64 b) {
    u64 d;
    asm("mul.rn.f32x2 %0, %1, %2;" : "=l"(d) : "l"(a), "l"(b));
    return d;
}
__device__ __forceinline__ u64 add2_(u64 a, u64 b) {
    u64 d;
    asm("add.rn.f32x2 %0, %1, %2;" : "=l"(d) : "l"(a), "l"(b));
    return d;
}

__global__ __launch_bounds__(128, 5)
void ssim_kernel(const float* __restrict__ img1,
                 const float* __restrict__ img2,
                 const float* __restrict__ win,
                 float* __restrict__ out)
{
    // Per-warp row buffer. Entry e holds col x0-2+e (e = 0..35), zeroed
    // at OOB columns by the producer-side masks.
    __shared__ float2 sSD[4][C][36];

    const int lane = threadIdx.x & 31;
    const int warp = threadIdx.x >> 5;
    const int b    = blockIdx.z;
    const int y0   = blockIdx.y * ROWS;
    const int x0   = blockIdx.x * BX + warp * 32;
    const int xo   = x0 + lane;           // output col (always < W)
    const int gx   = x0 - 2 + lane;       // main load col (may be < 0)
    const int gx2  = x0 + 30 + lane;      // halo load col (may be >= W)

    // Clamped load columns; masks zero the (s,d) stores for OOB cols.
    const int   gxc  = gx < 0 ? 0 : gx;               // gx <= 509 always
    const int   gx2c = gx2 > (W - 1) ? (W - 1) : gx2; // gx2 >= 30 always
    const float mm   = (gx  >= 0) ? 1.0f : 0.0f;
    const float mh   = (gx2 <  W) ? 1.0f : 0.0f;

    // Symmetric separable Gaussian: g[j] = w2d[2][j]/sqrt(w2d[2][2]),
    // g[0]==g[4], g[1]==g[3] bitwise. Keep 3 packed weights.
    const float gc = sqrtf(win[12]);
    const float g0 = __fdividef(win[10], gc);
    const float g1 = __fdividef(win[11], gc);
    const float g2 = __fdividef(win[12], gc);
    const u64 wg0 = pk2(g0, g0), wg1 = pk2(g1, g1), wg2 = pk2(g2, g2);

    // Rolling horizontal-filtered state: 5 row slots per channel (packed).
    u64 hSD[C][5], hSQ[C][5];

    // One-row-ahead prefetch registers (raw a, b; main + halo).
    float pa[C], pb[C], qa[C], qb[C];

    const int cb0 = b * (C * HW);         // channel-0 base for this batch

    // Running offsets: om/oh walk the unchecked rows y0..y0+31 (+W/step);
    // ob walks the output rows y0..y0+31 (+W/epilogue).
    int om = cb0 + y0 * W + gxc;
    int oh = cb0 + y0 * W + gx2c;
    int ob = (b * H + y0) * W + xo;

    auto loadrow_u = [&]() {              // interior rows: no checks at all
#pragma unroll
        for (int c = 0; c < C; ++c) {
            pa[c] = img1[om + c * HW];
            pb[c] = img2[om + c * HW];
            qa[c] = img1[oh + c * HW];
            qb[c] = img2[oh + c * HW];
        }
        om += W; oh += W;
    };
    auto loadrow_c = [&](int r) {         // top/bottom rows: zero if OOB
        const bool rok = (r >= 0) && (r < H);
        const int rr = (rok ? r : 0) * W;
        float ta[C], tb[C], ua[C], ub[C];
#pragma unroll
        for (int c = 0; c < C; ++c) {
            const int o = cb0 + c * HW + rr;
            ta[c] = img1[o + gxc];
            tb[c] = img2[o + gxc];
            ua[c] = img1[o + gx2c];
            ub[c] = img2[o + gx2c];
        }
#pragma unroll
        for (int c = 0; c < C; ++c) {
            pa[c] = rok ? ta[c] : 0.0f;
            pb[c] = rok ? tb[c] : 0.0f;
            qa[c] = rok ? ua[c] : 0.0f;
            qb[c] = rok ? ub[c] : 0.0f;
        }
    };

    const float C1 = 0.0001f;  // (0.01)^2
    const float C2 = 0.0009f;  // (0.03)^2

    // One pipeline step; S5 (slot) and EPI are compile-time.
    auto step = [&](int S5, bool EPI, auto&& prefetch) {
        // ---- store prefetched row to smem as masked (s,d) ----
        __syncwarp();
#pragma unroll
        for (int c = 0; c < C; ++c) {
            sSD[warp][c][lane] =
                make_float2((pa[c] + pb[c]) * mm, (pa[c] - pb[c]) * mm);
            if (lane < 4)
                sSD[warp][c][32 + lane] =
                    make_float2((qa[c] + qb[c]) * mh, (qa[c] - qb[c]) * mh);
        }
        __syncwarp();

        // ---- prefetch next row (hidden behind compute below) ----
        prefetch();

        // ---- horizontal symmetric 5-tap into slot S5 ----
#pragma unroll
        for (int c = 0; c < C; ++c) {
            const u64* p = (const u64*)&sSD[warp][c][0];
            const u64 p0 = p[lane],     p1 = p[lane + 1], p2 = p[lane + 2];
            const u64 p3 = p[lane + 3], p4 = p[lane + 4];
            u64 ssd = mul2_(add2_(p0, p4), wg0);
            ssd = fma2_(add2_(p1, p3), wg1, ssd);
            ssd = fma2_(p2, wg2, ssd);
            const u64 q0 = mul2_(p0, p0), q1 = mul2_(p1, p1);
            const u64 q2 = mul2_(p2, p2), q3 = mul2_(p3, p3);
            const u64 q4 = mul2_(p4, p4);
            u64 ssq = mul2_(add2_(q0, q4), wg0);
            ssq = fma2_(add2_(q1, q3), wg1, ssq);
            ssq = fma2_(q2, wg2, ssq);
            hSD[c][S5] = ssd;
            hSQ[c][S5] = ssq;
        }

        // ---- vertical symmetric 5-tap + epilogue ----
        if (EPI) {
            float num[C], den[C];
#pragma unroll
            for (int c = 0; c < C; ++c) {
                // rows s-4..s live at slots (S5+1)%5, .., (S5+4)%5, S5
                u64 vsd = mul2_(add2_(hSD[c][(S5 + 1) % 5], hSD[c][S5]), wg0);
                vsd = fma2_(add2_(hSD[c][(S5 + 2) % 5],
                                  hSD[c][(S5 + 4) % 5]), wg1, vsd);
                vsd = fma2_(hSD[c][(S5 + 3) % 5], wg2, vsd);
                u64 vsq = mul2_(add2_(hSQ[c][(S5 + 1) % 5], hSQ[c][S5]), wg0);
                vsq = fma2_(add2_(hSQ[c][(S5 + 2) % 5],
                                  hSQ[c][(S5 + 4) % 5]), wg1, vsq);
                vsq = fma2_(hSQ[c][(S5 + 3) % 5], wg2, vsq);

                float cs, cd, css, csd;
                up2(vsd, cs, cd);     // conv(s), conv(d)
                up2(vsq, css, csd);   // conv(s^2), conv(d^2)
                const float cs2 = cs * cs, cd2 = cd * cd;
                const float m12 = (cs2 - cd2) * 0.25f;   // mu1*mu2
                const float msq = (cs2 + cd2) * 0.5f;    // mu1^2+mu2^2
                const float cab = (css - csd) * 0.25f;   // conv(ab)
                const float csum = (css + csd) * 0.5f;   // conv(a2)+conv(b2)
                const float s12  = cab - m12;            // sigma12
                const float svar = csum - msq;           // var1+var2
                num[c] = (2.0f * m12 + C1) * (2.0f * s12 + C2);
                den[c] = (msq + C1) * (svar + C2);
            }
            const float d01   = den[0] * den[1];
            const float denom = d01 * den[2];
            float numer = num[2] * d01;
            numer = fmaf(num[0], den[1] * den[2], numer);
            numer = fmaf(num[1], den[0] * den[2], numer);
            out[ob] = __fdividef(numer, denom) * (1.0f / 3.0f);
            ob += W;
        }
    };

    // ---- pipeline: steps s = 0..35; S5 = s % 5 everywhere ----
    loadrow_c(y0 - 2);                                // row for step 0
    step(0, false, [&] { loadrow_c(y0 - 1); });       // s=0 (top, OOB ok)
    step(1, false, [&] { loadrow_u(); });             // s=1, row y0
    step(2, false, [&] { loadrow_u(); });             // s=2
    step(3, false, [&] { loadrow_u(); });             // s=3

    for (int it = 0; it < 5; ++it) {                  // s = 4..28
#pragma unroll
        for (int k = 0; k < 5; ++k)
            step((k + 4) % 5, true, [&] { loadrow_u(); });
    }

    step(4, true, [&] { loadrow_u(); });              // s=29
    step(0, true, [&] { loadrow_u(); });              // s=30
    step(1, true, [&] { loadrow_u(); });              // s=31
    step(2, true, [&] { loadrow_u(); });              // s=32 (row y0+31)
    step(3, true, [&] { loadrow_c(y0 + 32); });       // s=33 (bottom)
    step(4, true, [&] { loadrow_c(y0 + 33); });       // s=34 (bottom)
    step(0, true, [&] {});                            // s=35
}

extern "C" void kernel_launch(void* const* d_in, const int* in_sizes, int n_in,
                              void* d_out, int out_size)
{
    const float* img1 = (const float*)d_in[0];
    const float* img2 = (const float*)d_in[1];
    const float* win  = (const float*)d_in[2];
    float* out = (float*)d_out;

    dim3 grid(W / BX, H / ROWS, NB);  // (4, 16, 16) = 1024 blocks
    ssim_kernel<<<grid, 128>>>(img1, img2, win, out);
}

// round 16
// speedup vs baseline: 1.1481x; 1.1481x over previous
#include <cuda_runtime.h>

// ---------------------------------------------------------------------------
// SSIM (5x5 Gaussian, sigma=1.5, SAME zero padding), fused single kernel.
// R16 = R11 EXACTLY (loads, masked weights, ring, syncs, epilogue untouched)
//       with ROWS 32 -> 64:
//   - step overhead per output row: 36/32 -> 68/64 (12.5% -> 6.25%)
//   - grid 1024 -> 512 CTAs <= 592 resident @ 4 CTAs/SM: ONE wave,
//     no 73%-full second wave, one prologue transient per SM.
// ---------------------------------------------------------------------------

constexpr int W    = 512;
constexpr int H    = 512;
constexpr int C    = 3;
constexpr int NB   = 16;
constexpr int BX   = 128;   // output columns per block (4 warps x 32)
constexpr int ROWS = 64;    // output rows per block

typedef unsigned long long u64;

__device__ __forceinline__ u64 pk2(float lo, float hi) {
    u64 r;
    asm("mov.b64 %0, {%1, %2};" : "=l"(r) : "f"(lo), "f"(hi));
    return r;
}
__device__ __forceinline__ void up2(u64 v, float& lo, float& hi) {
    asm("mov.b64 {%0, %1}, %2;" : "=f"(lo), "=f"(hi) : "l"(v));
}
__device__ __forceinline__ u64 fma2_(u64 a, u64 b, u64 c) {
    u64 d;
    asm("fma.rn.f32x2 %0, %1, %2, %3;" : "=l"(d) : "l"(a), "l"(b), "l"(c));
    return d;
}
__device__ __forceinline__ u64 mul2_(u64 a, u64 b) {
    u64 d;
    asm("mul.rn.f32x2 %0, %1, %2;" : "=l"(d) : "l"(a), "l"(b));
    return d;
}

__global__ __launch_bounds__(128, 4)
void ssim_kernel(const float* __restrict__ img1,
                 const float* __restrict__ img2,
                 const float* __restrict__ win,
                 float* __restrict__ out)
{
    // Per-warp row buffer (36 cols = 32 + 4 halo): (s,d) pairs.
    __shared__ float2 sSD[4][C][36];

    const int lane = threadIdx.x & 31;
    const int warp = threadIdx.x >> 5;
    const int b    = blockIdx.z;
    const int y0   = blockIdx.y * ROWS;
    const int x0   = blockIdx.x * BX + warp * 32;
    const int xo   = x0 + lane;           // output col (always < W)
    const int gx   = x0 - 2 + lane;       // main load col (may be < 0)
    const int gx2  = x0 + 30 + lane;      // halo load col (may be >= W)

    // Clamped load columns (garbage values masked by consumer weights).
    const int gxc  = gx < 0 ? 0 : gx;
    const int gx2c = gx2 > (W - 1) ? (W - 1) : gx2;

    // Separable 1D Gaussian: g[j] = w2d[2][j] / sqrt(w2d[2][2]).
    const float gc = sqrtf(win[12]);
    u64 wg[5];    // vertical weights (unmasked)
    u64 wgm[5];   // horizontal weights, masked by this lane's tap validity
#pragma unroll
    for (int j = 0; j < 5; ++j) {
        const float gj = __fdividef(win[10 + j], gc);
        wg[j] = pk2(gj, gj);
        const int tapcol = xo - 2 + j;
        const float mj = (tapcol >= 0 && tapcol < W) ? gj : 0.0f;
        wgm[j] = pk2(mj, mj);
    }

    int cb[C];
#pragma unroll
    for (int c = 0; c < C; ++c) cb[c] = ((b * C + c) * H) * W;

    // Rolling horizontal-filtered state: 5 row slots per channel (packed).
    u64 hSD[C][5], hSQ[C][5];

    // One-row-ahead prefetch registers (raw a, b; main + halo).
    float pa[C], pb[C], qa[C], qb[C];

    auto loadrow_u = [&](int r) {       // interior rows: no checks at all
        const int rr = r * W;
#pragma unroll
        for (int c = 0; c < C; ++c) {
            const int o = cb[c] + rr;
            pa[c] = img1[o + gxc];
            pb[c] = img2[o + gxc];
            qa[c] = img1[o + gx2c];
            qb[c] = img2[o + gx2c];
        }
    };
    auto loadrow_c = [&](int r) {       // top/bottom rows: zero if OOB
        const bool rok = (r >= 0) && (r < H);
        const int rr = (rok ? r : 0) * W;
        float ta[C], tb[C], ua[C], ub[C];
#pragma unroll
        for (int c = 0; c < C; ++c) {
            const int o = cb[c] + rr;
            ta[c] = img1[o + gxc];
            tb[c] = img2[o + gxc];
            ua[c] = img1[o + gx2c];
            ub[c] = img2[o + gx2c];
        }
#pragma unroll
        for (int c = 0; c < C; ++c) {
            pa[c] = rok ? ta[c] : 0.0f;
            pb[c] = rok ? tb[c] : 0.0f;
            qa[c] = rok ? ua[c] : 0.0f;
            qb[c] = rok ? ub[c] : 0.0f;
        }
    };

    const float C1 = 0.0001f;  // (0.01)^2
    const float C2 = 0.0009f;  // (0.03)^2

    // One pipeline step. S5 = s % 5 compile-time so the ring stays in
    // registers. prefetch loads the row for step s+1.
    auto step = [&](int s, int S5, auto&& prefetch) {
        // ---- store prefetched row s to smem as (s,d) ----
        __syncwarp();
#pragma unroll
        for (int c = 0; c < C; ++c) {
            sSD[warp][c][lane] = make_float2(pa[c] + pb[c], pa[c] - pb[c]);
            if (lane < 4)
                sSD[warp][c][32 + lane] =
                    make_float2(qa[c] + qb[c], qa[c] - qb[c]);
        }
        __syncwarp();

        // ---- prefetch next row (hidden behind compute below) ----
        prefetch();

        // ---- horizontal 5-tap pass into slot S5 (masked weights) ----
#pragma unroll
        for (int c = 0; c < C; ++c) {
            const u64* p = (const u64*)&sSD[warp][c][0];
            u64 ssd = 0ull, ssq = 0ull;
#pragma unroll
            for (int j = 0; j < 5; ++j) {
                const u64 pp = p[lane + j];
                ssd = fma2_(pp, wgm[j], ssd);
                ssq = fma2_(mul2_(pp, pp), wgm[j], ssq);
            }
            hSD[c][S5] = ssd;
            hSQ[c][S5] = ssq;
        }

        // ---- vertical 5-tap + epilogue for output row y0+s-4 ----
        if (s >= 4) {
            float num[C], den[C];
#pragma unroll
            for (int c = 0; c < C; ++c) {
                u64 vsd = 0ull, vsq = 0ull;
#pragma unroll
                for (int j = 0; j < 5; ++j) {
                    const int slot = (S5 + 1 + j) % 5;  // row s-4+j
                    vsd = fma2_(hSD[c][slot], wg[j], vsd);
                    vsq = fma2_(hSQ[c][slot], wg[j], vsq);
                }
                float cs, cd, css, csd;
                up2(vsd, cs, cd);     // conv(s), conv(d)
                up2(vsq, css, csd);   // conv(s^2), conv(d^2)
                const float cs2 = cs * cs, cd2 = cd * cd;
                const float m12 = (cs2 - cd2) * 0.25f;   // mu1*mu2
                const float msq = (cs2 + cd2) * 0.5f;    // mu1^2+mu2^2
                const float cab = (css - csd) * 0.25f;   // conv(ab)
                const float csum = (css + csd) * 0.5f;   // conv(a2)+conv(b2)
                const float s12  = cab - m12;            // sigma12
                const float svar = csum - msq;           // var1+var2
                num[c] = (2.0f * m12 + C1) * (2.0f * s12 + C2);
                den[c] = (msq + C1) * (svar + C2);
            }
            const float d01   = den[0] * den[1];
            const float denom = d01 * den[2];
            float numer = num[2] * d01;
            numer = fmaf(num[0], den[1] * den[2], numer);
            numer = fmaf(num[1], den[0] * den[2], numer);
            const int y = y0 + s - 4;
            out[(b * H + y) * W + xo] =
                __fdividef(numer, denom) * (1.0f / 3.0f);
        }
    };

    // ---- pipeline: s = 0..67 (ROWS+4 steps), outputs at s = 4..67 ----
    loadrow_c(y0 - 2);                               // row for step 0
    step(0, 0, [&] { loadrow_c(y0 - 1); });          // top, may be OOB
    step(1, 1, [&] { loadrow_u(y0); });              // row y0 valid

    // Steady: s = 2..61 (prefetch rows y0+1 .. y0+60, always valid).
    for (int base = 2; base < 62; base += 5) {
#pragma unroll
        for (int k = 0; k < 5; ++k) {
            step(base + k, (k + 2) % 5,
                 [&] { loadrow_u(y0 - 1 + base + k); });
        }
    }

    step(62, 2, [&] { loadrow_u(y0 + 61); });        // valid (y0 <= 448)
    step(63, 3, [&] { loadrow_u(y0 + 62); });        // valid
    step(64, 4, [&] { loadrow_u(y0 + 63); });        // valid (<= 511)
    step(65, 0, [&] { loadrow_c(y0 + 64); });        // bottom, may be OOB
    step(66, 1, [&] { loadrow_c(y0 + 65); });        // bottom, may be OOB
    step(67, 2, [&] {});                             // last step
}

extern "C" void kernel_launch(void* const* d_in, const int* in_sizes, int n_in,
                              void* d_out, int out_size)
{
    const float* img1 = (const float*)d_in[0];
    const float* img2 = (const float*)d_in[1];
    const float* win  = (const float*)d_in[2];
    float* out = (float*)d_out;

    dim3 grid(W / BX, H / ROWS, NB);  // (4, 8, 16) = 512 blocks
    ssim_kernel<<<grid, 128>>>(img1, img2, win, out);
}

// round 17
// speedup vs baseline: 1.2247x; 1.0667x over previous
#include <cuda_runtime.h>

// ---------------------------------------------------------------------------
// SSIM (5x5 Gaussian, sigma=1.5, SAME zero padding), fused single kernel.
// R17 = R11 + DEPTH-2 prefetch: two register sets A/B (parity s&1); the row
//       stored at step s was loaded at step s-2 (~2 steps ~ 1300 cyc cover
//       vs ~650 at depth-1). Register budget reclaimed via symmetric
//       vertical weights (bitwise-exact) and compile-time channel strides.
// ---------------------------------------------------------------------------

constexpr int W    = 512;
constexpr int H    = 512;
constexpr int C    = 3;
constexpr int NB   = 16;
constexpr int BX   = 128;   // output columns per block (4 warps x 32)
constexpr int ROWS = 32;    // output rows per block
constexpr int HW   = H * W;

typedef unsigned long long u64;

__device__ __forceinline__ u64 pk2(float lo, float hi) {
    u64 r;
    asm("mov.b64 %0, {%1, %2};" : "=l"(r) : "f"(lo), "f"(hi));
    return r;
}
__device__ __forceinline__ void up2(u64 v, float& lo, float& hi) {
    asm("mov.b64 {%0, %1}, %2;" : "=f"(lo), "=f"(hi) : "l"(v));
}
__device__ __forceinline__ u64 fma2_(u64 a, u64 b, u64 c) {
    u64 d;
    asm("fma.rn.f32x2 %0, %1, %2, %3;" : "=l"(d) : "l"(a), "l"(b), "l"(c));
    return d;
}
__device__ __forceinline__ u64 mul2_(u64 a, u64 b) {
    u64 d;
    asm("mul.rn.f32x2 %0, %1, %2;" : "=l"(d) : "l"(a), "l"(b));
    return d;
}
__device__ __forceinline__ u64 add2_(u64 a, u64 b) {
    u64 d;
    asm("add.rn.f32x2 %0, %1, %2;" : "=l"(d) : "l"(a), "l"(b));
    return d;
}

struct Rowregs { float pa[C], pb[C], qa[C], qb[C]; };

__global__ __launch_bounds__(128, 4)
void ssim_kernel(const float* __restrict__ img1,
                 const float* __restrict__ img2,
                 const float* __restrict__ win,
                 float* __restrict__ out)
{
    // Per-warp row buffer (36 cols = 32 + 4 halo): (s,d) pairs.
    __shared__ float2 sSD[4][C][36];

    const int lane = threadIdx.x & 31;
    const int warp = threadIdx.x >> 5;
    const int b    = blockIdx.z;
    const int y0   = blockIdx.y * ROWS;
    const int x0   = blockIdx.x * BX + warp * 32;
    const int xo   = x0 + lane;           // output col (always < W)
    const int gx   = x0 - 2 + lane;       // main load col (may be < 0)
    const int gx2  = x0 + 30 + lane;      // halo load col (may be >= W)

    // Clamped load columns (garbage values masked by consumer weights).
    const int gxc  = gx < 0 ? 0 : gx;
    const int gx2c = gx2 > (W - 1) ? (W - 1) : gx2;

    // Separable 1D Gaussian: g[j] = w2d[2][j] / sqrt(w2d[2][2]).
    // Horizontal: per-lane masked weights (asymmetric at edges).
    // Vertical: symmetric (g0==g4, g1==g3 bitwise) -> 3 packed weights.
    const float gc = sqrtf(win[12]);
    u64 wgm[5];
#pragma unroll
    for (int j = 0; j < 5; ++j) {
        const float gj = __fdividef(win[10 + j], gc);
        const int tapcol = xo - 2 + j;
        const float mj = (tapcol >= 0 && tapcol < W) ? gj : 0.0f;
        wgm[j] = pk2(mj, mj);
    }
    const float g0 = __fdividef(win[10], gc);
    const float g1 = __fdividef(win[11], gc);
    const float g2 = __fdividef(win[12], gc);
    const u64 wv0 = pk2(g0, g0), wv1 = pk2(g1, g1), wv2 = pk2(g2, g2);

    const int cb0 = b * (C * HW);   // channel strides c*HW are compile-time

    // Rolling horizontal-filtered state: 5 row slots per channel (packed).
    u64 hSD[C][5], hSQ[C][5];

    // DEPTH-2 prefetch: two register sets, parity s&1.
    Rowregs A, B;

    auto loadrow_u = [&](Rowregs& R, int r) {   // interior rows: no checks
        const int rr = r * W;
#pragma unroll
        for (int c = 0; c < C; ++c) {
            const int o = cb0 + c * HW + rr;
            R.pa[c] = img1[o + gxc];
            R.pb[c] = img2[o + gxc];
            R.qa[c] = img1[o + gx2c];
            R.qb[c] = img2[o + gx2c];
        }
    };
    auto loadrow_c = [&](Rowregs& R, int r) {   // top/bottom: zero if OOB
        const bool rok = (r >= 0) && (r < H);
        const int rr = (rok ? r : 0) * W;
        float ta[C], tb[C], ua[C], ub[C];
#pragma unroll
        for (int c = 0; c < C; ++c) {
            const int o = cb0 + c * HW + rr;
            ta[c] = img1[o + gxc];
            tb[c] = img2[o + gxc];
            ua[c] = img1[o + gx2c];
            ub[c] = img2[o + gx2c];
        }
#pragma unroll
        for (int c = 0; c < C; ++c) {
            R.pa[c] = rok ? ta[c] : 0.0f;
            R.pb[c] = rok ? tb[c] : 0.0f;
            R.qa[c] = rok ? ua[c] : 0.0f;
            R.qb[c] = rok ? ub[c] : 0.0f;
        }
    };

    const float C1 = 0.0001f;  // (0.01)^2
    const float C2 = 0.0009f;  // (0.03)^2

    // One pipeline step. R holds row s (loaded at step s-2). prefetch
    // reloads R with row s+2. S5 = s % 5 compile-time.
    auto step = [&](int s, int S5, Rowregs& R, auto&& prefetch) {
        // ---- store row s to smem as (s,d) ----
        __syncwarp();
#pragma unroll
        for (int c = 0; c < C; ++c) {
            sSD[warp][c][lane] =
                make_float2(R.pa[c] + R.pb[c], R.pa[c] - R.pb[c]);
            if (lane < 4)
                sSD[warp][c][32 + lane] =
                    make_float2(R.qa[c] + R.qb[c], R.qa[c] - R.qb[c]);
        }
        __syncwarp();

        // ---- issue loads for row s+2 into R (2 steps of cover) ----
        prefetch();

        // ---- horizontal 5-tap pass into slot S5 (masked weights) ----
#pragma unroll
        for (int c = 0; c < C; ++c) {
            const u64* p = (const u64*)&sSD[warp][c][0];
            u64 ssd = 0ull, ssq = 0ull;
#pragma unroll
            for (int j = 0; j < 5; ++j) {
                const u64 pp = p[lane + j];
                ssd = fma2_(pp, wgm[j], ssd);
                ssq = fma2_(mul2_(pp, pp), wgm[j], ssq);
            }
            hSD[c][S5] = ssd;
            hSQ[c][S5] = ssq;
        }

        // ---- vertical symmetric 5-tap + epilogue for row y0+s-4 ----
        if (s >= 4) {
            float num[C], den[C];
#pragma unroll
            for (int c = 0; c < C; ++c) {
                // rows s-4..s at slots (S5+1+j)%5, j=0..4; pair j with 4-j.
                const u64 a0 = hSD[c][(S5 + 1) % 5], a4 = hSD[c][S5];
                const u64 a1 = hSD[c][(S5 + 2) % 5], a3 = hSD[c][(S5 + 4) % 5];
                const u64 a2 = hSD[c][(S5 + 3) % 5];
                u64 vsd = mul2_(add2_(a0, a4), wv0);
                vsd = fma2_(add2_(a1, a3), wv1, vsd);
                vsd = fma2_(a2, wv2, vsd);
                const u64 b0 = hSQ[c][(S5 + 1) % 5], b4 = hSQ[c][S5];
                const u64 b1 = hSQ[c][(S5 + 2) % 5], b3 = hSQ[c][(S5 + 4) % 5];
                const u64 b2 = hSQ[c][(S5 + 3) % 5];
                u64 vsq = mul2_(add2_(b0, b4), wv0);
                vsq = fma2_(add2_(b1, b3), wv1, vsq);
                vsq = fma2_(b2, wv2, vsq);

                float cs, cd, css, csd;
                up2(vsd, cs, cd);     // conv(s), conv(d)
                up2(vsq, css, csd);   // conv(s^2), conv(d^2)
                const float cs2 = cs * cs, cd2 = cd * cd;
                const float m12 = (cs2 - cd2) * 0.25f;   // mu1*mu2
                const float msq = (cs2 + cd2) * 0.5f;    // mu1^2+mu2^2
                const float cab = (css - csd) * 0.25f;   // conv(ab)
                const float csum = (css + csd) * 0.5f;   // conv(a2)+conv(b2)
                const float s12  = cab - m12;            // sigma12
                const float svar = csum - msq;           // var1+var2
                num[c] = (2.0f * m12 + C1) * (2.0f * s12 + C2);
                den[c] = (msq + C1) * (svar + C2);
            }
            const float d01   = den[0] * den[1];
            const float denom = d01 * den[2];
            float numer = num[2] * d01;
            numer = fmaf(num[0], den[1] * den[2], numer);
            numer = fmaf(num[1], den[0] * den[2], numer);
            const int y = y0 + s - 4;
            out[(b * H + y) * W + xo] =
                __fdividef(numer, denom) * (1.0f / 3.0f);
        }
    };

    // ---- pipeline: steps s = 0..35; step s prefetches row y0+s ----
    loadrow_c(A, y0 - 2);   // row for step 0
    loadrow_c(B, y0 - 1);   // row for step 1

    step(0, 0, A, [&] { loadrow_u(A, y0 + 0); });
    step(1, 1, B, [&] { loadrow_u(B, y0 + 1); });
    step(2, 2, A, [&] { loadrow_u(A, y0 + 2); });
    step(3, 3, B, [&] { loadrow_u(B, y0 + 3); });

    // Steady: s = 4..23 (prefetch rows y0+4 .. y0+23, always valid).
    for (int base = 4; base < 24; base += 10) {
#pragma unroll
        for (int k = 0; k < 10; ++k) {
            Rowregs& R = (k & 1) ? B : A;
            step(base + k, (k + 4) % 5, R,
                 [&] { loadrow_u(R, y0 + base + k); });
        }
    }

    // s = 24..33: rows y0+24 .. y0+31 unchecked; y0+32, y0+33 checked.
    {
#pragma unroll
        for (int k = 0; k < 10; ++k) {
            Rowregs& R = (k & 1) ? B : A;
            step(24 + k, (k + 4) % 5, R, [&] {
                if (k < 8) loadrow_u(R, y0 + 24 + k);
                else       loadrow_c(R, y0 + 24 + k);
            });
        }
    }

    step(34, 4, A, [&] {});   // A holds row y0+32 (loaded at s=32)
    step(35, 0, B, [&] {});   // B holds row y0+33 (loaded at s=33)
}

extern "C" void kernel_launch(void* const* d_in, const int* in_sizes, int n_in,
                              void* d_out, int out_size)
{
    const float* img1 = (const float*)d_in[0];
    const float* img2 = (const float*)d_in[1];
    const float* win  = (const float*)d_in[2];
    float* out = (float*)d_out;

    dim3 grid(W / BX, H / ROWS, NB);  // (4, 16, 16) = 1024 blocks
    ssim_kernel<<<grid, 128>>>(img1, img2, win, out);
}